// round 3
// baseline (speedup 1.0000x reference)
#include <cuda_runtime.h>
#include <math.h>

#define B_ 4
#define S_ 2048
#define D_ 1024
#define H_ 16
#define A_ 64

// Scratch for projected qh/kh/vh: [3][B,H,S,A] fp32 = 100.7 MB total.
__device__ float g_proj[3][(size_t)B_ * H_ * S_ * A_];

// ---------------------------------------------------------------------------
// Kernel A: per-head projection GEMM + bias, double-buffered smem.
// C[s0..s0+63][0..63] = X[b, s0.., :] (64x1024) @ W[h] (1024x64) + bias[h]
// Block: 256 threads as 16x16, each owns a 4x4 micro-tile. BK=16.
// grid = (S/64, H, 3*B); z encodes (matrix m, batch b).
// ---------------------------------------------------------------------------
__global__ __launch_bounds__(256)
void proj_kernel(const float* __restrict__ q, const float* __restrict__ k,
                 const float* __restrict__ v,
                 const float* __restrict__ Wq, const float* __restrict__ bq,
                 const float* __restrict__ Wk, const float* __restrict__ bk,
                 const float* __restrict__ Wv, const float* __restrict__ bv)
{
    __shared__ float Xs[2][64][16];
    __shared__ float Ws[2][16][68];   // pad to 68 so float4 rows stay 16B-aligned

    const int s0 = blockIdx.x * 64;
    const int h  = blockIdx.y;
    const int mz = blockIdx.z;     // 0..11
    const int m  = mz >> 2;        // 0=q,1=k,2=v   (B_=4)
    const int b  = mz & 3;

    const float *X, *W, *bias;
    if (m == 0)      { X = q; W = Wq; bias = bq; }
    else if (m == 1) { X = k; W = Wk; bias = bk; }
    else             { X = v; W = Wv; bias = bv; }
    X    += (size_t)b * S_ * D_;
    W    += (size_t)h * D_ * A_;
    bias += h * A_;
    float* out = g_proj[m] + (((size_t)b * H_ + h) * S_ + s0) * A_;

    const int tid = threadIdx.x;
    const int tx  = tid & 15;
    const int ty  = tid >> 4;

    // global->smem load assignments
    const int xr = tid >> 2;            // 0..63  (row of X tile)
    const int xc = (tid & 3) << 2;      // 0,4,8,12
    const int wr = tid >> 4;            // 0..15  (row of W tile)
    const int wc = (tid & 15) << 2;     // 0..60

    float acc[4][4] = {};

    // prologue: load tile 0
    {
        float4 xv = *(const float4*)(X + (size_t)(s0 + xr) * D_ + xc);
        float4 wv = *(const float4*)(W + (size_t)(wr) * A_ + wc);
        *(float4*)&Xs[0][xr][xc] = xv;
        *(float4*)&Ws[0][wr][wc] = wv;
    }
    __syncthreads();

    int buf = 0;
    for (int d0 = 0; d0 < D_; d0 += 16) {
        float4 xv, wv;
        const bool have_next = (d0 + 16 < D_);
        if (have_next) {
            xv = *(const float4*)(X + (size_t)(s0 + xr) * D_ + d0 + 16 + xc);
            wv = *(const float4*)(W + (size_t)(d0 + 16 + wr) * A_ + wc);
        }

        #pragma unroll
        for (int kk = 0; kk < 16; kk++) {
            float x0 = Xs[buf][ty * 4 + 0][kk];
            float x1 = Xs[buf][ty * 4 + 1][kk];
            float x2 = Xs[buf][ty * 4 + 2][kk];
            float x3 = Xs[buf][ty * 4 + 3][kk];
            float4 w4 = *(const float4*)&Ws[buf][kk][tx * 4];
            acc[0][0] += x0 * w4.x; acc[0][1] += x0 * w4.y; acc[0][2] += x0 * w4.z; acc[0][3] += x0 * w4.w;
            acc[1][0] += x1 * w4.x; acc[1][1] += x1 * w4.y; acc[1][2] += x1 * w4.z; acc[1][3] += x1 * w4.w;
            acc[2][0] += x2 * w4.x; acc[2][1] += x2 * w4.y; acc[2][2] += x2 * w4.z; acc[2][3] += x2 * w4.w;
            acc[3][0] += x3 * w4.x; acc[3][1] += x3 * w4.y; acc[3][2] += x3 * w4.z; acc[3][3] += x3 * w4.w;
        }

        if (have_next) {
            *(float4*)&Xs[buf ^ 1][xr][xc] = xv;   // writers hit buf^1, readers done with it
            *(float4*)&Ws[buf ^ 1][wr][wc] = wv;
            buf ^= 1;
            __syncthreads();
        }
    }

    float4 bb = *(const float4*)(bias + tx * 4);
    #pragma unroll
    for (int i = 0; i < 4; i++) {
        float4 o4 = make_float4(acc[i][0] + bb.x, acc[i][1] + bb.y,
                                acc[i][2] + bb.z, acc[i][3] + bb.w);
        *(float4*)(out + (size_t)(ty * 4 + i) * A_ + tx * 4) = o4;
    }
}

// ---------------------------------------------------------------------------
// Kernel B: flash attention over one (b, h, 64-row Q tile).
// smem: Qs[64][64], KP[64][65] (K tile, then reused for P), Vs[64][64]
// Online softmax with per-row stats reduced across the 16 lanes of a row group.
// Writes output directly in [B, S, H*A] layout, divided by l.
// ---------------------------------------------------------------------------
#define QS_OFF  0
#define KP_OFF  (64 * 64)
#define VS_OFF  (64 * 64 + 64 * 65)
#define SMEM_ATTN_BYTES ((64 * 64 + 64 * 65 + 64 * 64) * (int)sizeof(float))

__global__ __launch_bounds__(256)
void attn_kernel(float* __restrict__ out)
{
    extern __shared__ float sm[];
    float* Qs = sm + QS_OFF;   // [r][a]  pitch 64
    float* KP = sm + KP_OFF;   // K: [c][a] pitch 65 ; later P: [r][kv] pitch 65
    float* Vs = sm + VS_OFF;   // [kv][a] pitch 64

    const int q0 = blockIdx.x * 64;
    const int h  = blockIdx.y;
    const int b  = blockIdx.z;
    const size_t base = ((size_t)b * H_ + h) * S_ * A_;
    const float* Q = g_proj[0] + base;
    const float* K = g_proj[1] + base;
    const float* V = g_proj[2] + base;

    const int tid = threadIdx.x;
    const int tx  = tid & 15;
    const int ty  = tid >> 4;

    // load Q tile (stays resident)
    for (int t = tid; t < 64 * 16; t += 256) {
        int r = t >> 4;
        int c = (t & 15) << 2;
        *(float4*)&Qs[r * 64 + c] = *(const float4*)(Q + (size_t)(q0 + r) * A_ + c);
    }

    float o[4][4] = {};
    float mrow[4] = { -1e30f, -1e30f, -1e30f, -1e30f };
    float lrow[4] = {};

    for (int kv0 = 0; kv0 < S_; kv0 += 64) {
        __syncthreads();   // prev iter's P/V reads done; Qs visible on first iter
        for (int t = tid; t < 64 * 16; t += 256) {
            int r = t >> 4;
            int c = (t & 15) << 2;
            float4 k4 = *(const float4*)(K + (size_t)(kv0 + r) * A_ + c);
            KP[r * 65 + c + 0] = k4.x;
            KP[r * 65 + c + 1] = k4.y;
            KP[r * 65 + c + 2] = k4.z;
            KP[r * 65 + c + 3] = k4.w;
            *(float4*)&Vs[r * 64 + c] = *(const float4*)(V + (size_t)(kv0 + r) * A_ + c);
        }
        __syncthreads();

        // S tile: s[i][j] = sum_a Qs[ty4+i][a] * K[tx4+j][a]
        float s[4][4] = {};
        #pragma unroll 8
        for (int a = 0; a < 64; a++) {
            float qv0 = Qs[(ty * 4 + 0) * 64 + a];
            float qv1 = Qs[(ty * 4 + 1) * 64 + a];
            float qv2 = Qs[(ty * 4 + 2) * 64 + a];
            float qv3 = Qs[(ty * 4 + 3) * 64 + a];
            float kv0v = KP[(tx * 4 + 0) * 65 + a];
            float kv1v = KP[(tx * 4 + 1) * 65 + a];
            float kv2v = KP[(tx * 4 + 2) * 65 + a];
            float kv3v = KP[(tx * 4 + 3) * 65 + a];
            s[0][0] += qv0 * kv0v; s[0][1] += qv0 * kv1v; s[0][2] += qv0 * kv2v; s[0][3] += qv0 * kv3v;
            s[1][0] += qv1 * kv0v; s[1][1] += qv1 * kv1v; s[1][2] += qv1 * kv2v; s[1][3] += qv1 * kv3v;
            s[2][0] += qv2 * kv0v; s[2][1] += qv2 * kv1v; s[2][2] += qv2 * kv2v; s[2][3] += qv2 * kv3v;
            s[3][0] += qv3 * kv0v; s[3][1] += qv3 * kv1v; s[3][2] += qv3 * kv2v; s[3][3] += qv3 * kv3v;
        }

        // online softmax update (row group = 16 lanes sharing ty, contiguous half-warp)
        float alpha[4], rsum[4];
        #pragma unroll
        for (int i = 0; i < 4; i++) {
            float mx = fmaxf(fmaxf(s[i][0], s[i][1]), fmaxf(s[i][2], s[i][3]));
            #pragma unroll
            for (int off = 8; off >= 1; off >>= 1)
                mx = fmaxf(mx, __shfl_xor_sync(0xffffffffu, mx, off));
            float mnew = fmaxf(mrow[i], mx);
            alpha[i] = __expf(mrow[i] - mnew);
            mrow[i] = mnew;
            float sum = 0.0f;
            #pragma unroll
            for (int j = 0; j < 4; j++) {
                s[i][j] = __expf(s[i][j] - mnew);
                sum += s[i][j];
            }
            #pragma unroll
            for (int off = 8; off >= 1; off >>= 1)
                sum += __shfl_xor_sync(0xffffffffu, sum, off);
            rsum[i] = sum;
        }
        #pragma unroll
        for (int i = 0; i < 4; i++) {
            lrow[i] = lrow[i] * alpha[i] + rsum[i];
            #pragma unroll
            for (int j = 0; j < 4; j++) o[i][j] *= alpha[i];
        }

        // stage P into KP (K reads are done)
        __syncthreads();
        #pragma unroll
        for (int i = 0; i < 4; i++)
            #pragma unroll
            for (int j = 0; j < 4; j++)
                KP[(ty * 4 + i) * 65 + tx * 4 + j] = s[i][j];
        __syncthreads();

        // O += P @ V
        #pragma unroll 8
        for (int kv = 0; kv < 64; kv++) {
            float p0 = KP[(ty * 4 + 0) * 65 + kv];
            float p1 = KP[(ty * 4 + 1) * 65 + kv];
            float p2 = KP[(ty * 4 + 2) * 65 + kv];
            float p3 = KP[(ty * 4 + 3) * 65 + kv];
            float v0 = Vs[kv * 64 + tx * 4 + 0];
            float v1 = Vs[kv * 64 + tx * 4 + 1];
            float v2 = Vs[kv * 64 + tx * 4 + 2];
            float v3 = Vs[kv * 64 + tx * 4 + 3];
            o[0][0] += p0 * v0; o[0][1] += p0 * v1; o[0][2] += p0 * v2; o[0][3] += p0 * v3;
            o[1][0] += p1 * v0; o[1][1] += p1 * v1; o[1][2] += p1 * v2; o[1][3] += p1 * v3;
            o[2][0] += p2 * v0; o[2][1] += p2 * v1; o[2][2] += p2 * v2; o[2][3] += p2 * v3;
            o[3][0] += p3 * v0; o[3][1] += p3 * v1; o[3][2] += p3 * v2; o[3][3] += p3 * v3;
        }
    }

    // epilogue: divide by l, write [B, S, H*A]
    float* outp = out + ((size_t)b * S_ + q0) * (H_ * A_) + h * A_;
    #pragma unroll
    for (int i = 0; i < 4; i++) {
        float inv = 1.0f / lrow[i];
        float4 o4 = make_float4(o[i][0] * inv, o[i][1] * inv,
                                o[i][2] * inv, o[i][3] * inv);
        *(float4*)(outp + (size_t)(ty * 4 + i) * (H_ * A_) + tx * 4) = o4;
    }
}

// ---------------------------------------------------------------------------
extern "C" void kernel_launch(void* const* d_in, const int* in_sizes, int n_in,
                              void* d_out, int out_size)
{
    const float* q  = (const float*)d_in[0];
    const float* k  = (const float*)d_in[1];
    const float* v  = (const float*)d_in[2];
    const float* Wq = (const float*)d_in[3];
    const float* bq = (const float*)d_in[4];
    const float* Wk = (const float*)d_in[5];
    const float* bk = (const float*)d_in[6];
    const float* Wv = (const float*)d_in[7];
    const float* bv = (const float*)d_in[8];
    float* out = (float*)d_out;

    static bool attr_set = false;  // idempotent attribute set (not a work guard)
    if (!attr_set) {
        cudaFuncSetAttribute(attn_kernel,
                             cudaFuncAttributeMaxDynamicSharedMemorySize,
                             SMEM_ATTN_BYTES);
        attr_set = true;
    }

    dim3 pgrid(S_ / 64, H_, 3 * B_);
    proj_kernel<<<pgrid, 256>>>(q, k, v, Wq, bq, Wk, bk, Wv, bv);

    dim3 agrid(S_ / 64, H_, B_);
    attn_kernel<<<agrid, 256, SMEM_ATTN_BYTES>>>(out);
}

// round 4
// speedup vs baseline: 1.1951x; 1.1951x over previous
#include <cuda_runtime.h>
#include <math.h>
#include <stdint.h>

#define B_ 4
#define S_ 2048
#define D_ 1024
#define H_ 16
#define A_ 64

// qh/kh stored TRANSPOSED per head: [b][h][a][s].  vh natural: [b][h][s][a].
__device__ float g_proj[3][(size_t)B_ * H_ * S_ * A_];

// ---------------- cp.async helpers ----------------
__device__ __forceinline__ uint32_t smem_u32(const void* p) {
    return (uint32_t)__cvta_generic_to_shared(p);
}
__device__ __forceinline__ void cp16(uint32_t s, const void* g) {
    asm volatile("cp.async.cg.shared.global [%0], [%1], 16;\n" :: "r"(s), "l"(g));
}
#define CP_COMMIT() asm volatile("cp.async.commit_group;\n" ::: "memory")
#define CP_WAIT0()  asm volatile("cp.async.wait_group 0;\n" ::: "memory")

// ===========================================================================
// Kernel A: projection GEMM + bias.  Tile: 128 rows(s) x 128 cols(2 heads*64).
// 256 threads, 8x8 micro-tile (rows ty*4+{0..3,64..67}, cols tx*4+{0..3,64..67}).
// BK=32, 2-stage cp.async double buffer.
// q/k outputs written transposed [h][a][s]; v natural [h][s][a].
// grid = (S/128, H/2, 3*B)
// ===========================================================================
#define PK_BK   32
#define PK_XP   36     // Xs row pitch (floats)
#define PK_WP   132    // Ws row pitch
#define PK_XS_FL (128 * PK_XP)          // 4608 floats / stage
#define PK_WS_FL (PK_BK * PK_WP)        // 4224 floats / stage
#define PK_SMEM_FL (2 * PK_XS_FL + 2 * PK_WS_FL)
#define PK_SMEM_BYTES (PK_SMEM_FL * 4)  // 70656 B

__global__ __launch_bounds__(256, 2)
void proj_kernel(const float* __restrict__ q, const float* __restrict__ k,
                 const float* __restrict__ v,
                 const float* __restrict__ Wq, const float* __restrict__ bq,
                 const float* __restrict__ Wk, const float* __restrict__ bk,
                 const float* __restrict__ Wv, const float* __restrict__ bv)
{
    extern __shared__ float ps[];
    const uint32_t smb = smem_u32(ps);

    const int s0 = blockIdx.x * 128;
    const int h0 = blockIdx.y * 2;
    const int mz = blockIdx.z;
    const int m  = mz >> 2;
    const int b  = mz & 3;

    const float *X, *W, *bias;
    if (m == 0)      { X = q; W = Wq; bias = bq; }
    else if (m == 1) { X = k; W = Wk; bias = bk; }
    else             { X = v; W = Wv; bias = bv; }
    X += (size_t)b * S_ * D_;

    const int tid = threadIdx.x;
    const int tx  = tid & 15;
    const int ty  = tid >> 4;

    float acc[8][8] = {};

    // ---- stage loader ----
    auto issue_stage = [&](int st, int d0) {
        uint32_t xb = smb + (uint32_t)(st * PK_XS_FL) * 4u;
        #pragma unroll
        for (int u = 0; u < 4; u++) {
            int cc = u * 256 + tid;
            int r  = cc >> 3;
            int k4 = (cc & 7) * 4;
            cp16(xb + (uint32_t)(r * PK_XP + k4) * 4u,
                 X + (size_t)(s0 + r) * D_ + d0 + k4);
        }
        uint32_t wb = smb + (uint32_t)(2 * PK_XS_FL + st * PK_WS_FL) * 4u;
        #pragma unroll
        for (int u = 0; u < 4; u++) {
            int cc = u * 256 + tid;
            int kr = cc >> 5;
            int c  = (cc & 31) * 4;
            int hh = c >> 6;
            int a  = c & 63;
            cp16(wb + (uint32_t)(kr * PK_WP + c) * 4u,
                 W + ((size_t)(h0 + hh) * D_ + d0 + kr) * A_ + a);
        }
        CP_COMMIT();
    };

    issue_stage(0, 0);

    const int NIT = D_ / PK_BK;   // 32
    for (int it = 0; it < NIT; it++) {
        const int st = it & 1;
        CP_WAIT0();
        __syncthreads();
        if (it + 1 < NIT) issue_stage(st ^ 1, (it + 1) * PK_BK);

        const float* xb = ps + st * PK_XS_FL;
        const float* wb = ps + 2 * PK_XS_FL + st * PK_WS_FL;

        #pragma unroll
        for (int k4 = 0; k4 < PK_BK / 4; k4++) {
            float xr[8][4];
            #pragma unroll
            for (int i = 0; i < 8; i++) {
                int r = ty * 4 + (i & 3) + (i >> 2) * 64;
                *(float4*)xr[i] = *(const float4*)&xb[r * PK_XP + k4 * 4];
            }
            #pragma unroll
            for (int u = 0; u < 4; u++) {
                float4 wa = *(const float4*)&wb[(k4 * 4 + u) * PK_WP + tx * 4];
                float4 wc = *(const float4*)&wb[(k4 * 4 + u) * PK_WP + tx * 4 + 64];
                #pragma unroll
                for (int i = 0; i < 8; i++) {
                    float xi = xr[i][u];
                    acc[i][0] += xi * wa.x; acc[i][1] += xi * wa.y;
                    acc[i][2] += xi * wa.z; acc[i][3] += xi * wa.w;
                    acc[i][4] += xi * wc.x; acc[i][5] += xi * wc.y;
                    acc[i][6] += xi * wc.z; acc[i][7] += xi * wc.w;
                }
            }
        }
        __syncthreads();
    }

    // ---- epilogue: bias + store ----
    if (m < 2) {
        // transposed layout [b][h][a][s]
        float* outT = g_proj[m];
        #pragma unroll
        for (int j4 = 0; j4 < 2; j4++) {
            int h = h0 + j4;
            #pragma unroll
            for (int jj = 0; jj < 4; jj++) {
                float bvv = bias[h * A_ + tx * 4 + jj];
                #pragma unroll
                for (int i4 = 0; i4 < 2; i4++) {
                    float4 val = make_float4(acc[i4 * 4 + 0][j4 * 4 + jj] + bvv,
                                             acc[i4 * 4 + 1][j4 * 4 + jj] + bvv,
                                             acc[i4 * 4 + 2][j4 * 4 + jj] + bvv,
                                             acc[i4 * 4 + 3][j4 * 4 + jj] + bvv);
                    size_t off = ((size_t)((b * H_ + h) * A_) + tx * 4 + jj) * S_
                                 + s0 + ty * 4 + i4 * 64;
                    *(float4*)(outT + off) = val;
                }
            }
        }
    } else {
        float* outN = g_proj[2];
        #pragma unroll
        for (int i = 0; i < 8; i++) {
            int r = s0 + ty * 4 + (i & 3) + (i >> 2) * 64;
            #pragma unroll
            for (int j4 = 0; j4 < 2; j4++) {
                int h = h0 + j4;
                float4 bv4 = *(const float4*)&bias[h * A_ + tx * 4];
                float4 val = make_float4(acc[i][j4 * 4 + 0] + bv4.x,
                                         acc[i][j4 * 4 + 1] + bv4.y,
                                         acc[i][j4 * 4 + 2] + bv4.z,
                                         acc[i][j4 * 4 + 3] + bv4.w);
                size_t off = ((size_t)(b * H_ + h) * S_ + r) * A_ + tx * 4;
                *(float4*)(outN + off) = val;
            }
        }
    }
}

// ===========================================================================
// Kernel B: flash attention.  Block = (b, h, 128 Q rows). 256 threads.
// S-tile 128x128, 8x8 micro-tile; O-tile 128x64, 8x4 micro-tile.
// Q/K in smem a-major (from transposed g_proj), V natural, P staged fp32.
// cp.async prefetch of K(t+1), V(t+1) (V double-buffered) during PV.
// ===========================================================================
#define AT_QP 132                 // Q/K smem pitch (cols = 128 s)
#define AT_VP 68                  // V smem pitch (cols = 64 a)
#define AT_PP 132                 // P smem pitch
#define AT_QS 0
#define AT_KS (64 * AT_QP)                      // 8448
#define AT_VS (AT_KS + 64 * AT_QP)              // 16896
#define AT_VSTG (128 * AT_VP)                   // 8704 per stage
#define AT_PS (AT_VS + 2 * AT_VSTG)             // 34304
#define AT_SMEM_FL (AT_PS + 128 * AT_PP)        // 51200
#define AT_SMEM_BYTES (AT_SMEM_FL * 4)          // 204800 B

__global__ __launch_bounds__(256, 1)
void attn_kernel(float* __restrict__ out)
{
    extern __shared__ float sm[];
    const uint32_t smb = smem_u32(sm);

    const int q0 = blockIdx.x * 128;
    const int h  = blockIdx.y;
    const int b  = blockIdx.z;

    const float* Qg = g_proj[0] + (size_t)(b * H_ + h) * A_ * S_;  // [a][s]
    const float* Kg = g_proj[1] + (size_t)(b * H_ + h) * A_ * S_;  // [a][s]
    const float* Vg = g_proj[2] + (size_t)(b * H_ + h) * S_ * A_;  // [s][a]

    const int tid = threadIdx.x;
    const int tx  = tid & 15;
    const int ty  = tid >> 4;

    auto load_k = [&](int t) {
        #pragma unroll
        for (int u = 0; u < 8; u++) {
            int cc = u * 256 + tid;
            int a  = cc >> 5;
            int s4 = (cc & 31) * 4;
            cp16(smb + (uint32_t)(AT_KS + a * AT_QP + s4) * 4u,
                 Kg + (size_t)a * S_ + t * 128 + s4);
        }
    };
    auto load_v = [&](int t, int vb) {
        #pragma unroll
        for (int u = 0; u < 8; u++) {
            int cc = u * 256 + tid;
            int r  = cc >> 4;
            int a4 = (cc & 15) * 4;
            cp16(smb + (uint32_t)(AT_VS + vb * AT_VSTG + r * AT_VP + a4) * 4u,
                 Vg + (size_t)(t * 128 + r) * A_ + a4);
        }
    };

    // prologue: Q + K(0) + V(0)
    #pragma unroll
    for (int u = 0; u < 8; u++) {
        int cc = u * 256 + tid;
        int a  = cc >> 5;
        int s4 = (cc & 31) * 4;
        cp16(smb + (uint32_t)(AT_QS + a * AT_QP + s4) * 4u,
             Qg + (size_t)a * S_ + q0 + s4);
    }
    load_k(0);
    load_v(0, 0);
    CP_COMMIT();

    float o[8][4] = {};
    float mrow[8], lrow[8];
    #pragma unroll
    for (int i = 0; i < 8; i++) { mrow[i] = -1e30f; lrow[i] = 0.0f; }

    const int NT = S_ / 128;   // 16
    for (int t = 0; t < NT; t++) {
        const int vb = t & 1;
        CP_WAIT0();
        __syncthreads();

        // ---- S tile:  s[i][j] = sum_a Q[a][r_i] * K[a][c_j] ----
        float s[8][8] = {};
        #pragma unroll 4
        for (int a = 0; a < 64; a++) {
            float4 qa = *(const float4*)&sm[AT_QS + a * AT_QP + ty * 4];
            float4 qb = *(const float4*)&sm[AT_QS + a * AT_QP + ty * 4 + 64];
            float4 ka = *(const float4*)&sm[AT_KS + a * AT_QP + tx * 4];
            float4 kb = *(const float4*)&sm[AT_KS + a * AT_QP + tx * 4 + 64];
            float qv[8] = {qa.x, qa.y, qa.z, qa.w, qb.x, qb.y, qb.z, qb.w};
            float kv[8] = {ka.x, ka.y, ka.z, ka.w, kb.x, kb.y, kb.z, kb.w};
            #pragma unroll
            for (int i = 0; i < 8; i++)
                #pragma unroll
                for (int j = 0; j < 8; j++)
                    s[i][j] += qv[i] * kv[j];
        }

        // ---- online softmax ----
        #pragma unroll
        for (int i = 0; i < 8; i++) {
            float mx = s[i][0];
            #pragma unroll
            for (int j = 1; j < 8; j++) mx = fmaxf(mx, s[i][j]);
            #pragma unroll
            for (int off = 8; off >= 1; off >>= 1)
                mx = fmaxf(mx, __shfl_xor_sync(0xffffffffu, mx, off));
            float mnew = fmaxf(mrow[i], mx);
            float al   = __expf(mrow[i] - mnew);
            mrow[i] = mnew;
            float sum = 0.0f;
            #pragma unroll
            for (int j = 0; j < 8; j++) {
                s[i][j] = __expf(s[i][j] - mnew);
                sum += s[i][j];
            }
            #pragma unroll
            for (int off = 8; off >= 1; off >>= 1)
                sum += __shfl_xor_sync(0xffffffffu, sum, off);
            lrow[i] = lrow[i] * al + sum;
            #pragma unroll
            for (int jj = 0; jj < 4; jj++) o[i][jj] *= al;
        }

        __syncthreads();   // K reads + prev P reads done everywhere
        if (t + 1 < NT) { load_k(t + 1); load_v(t + 1, vb ^ 1); CP_COMMIT(); }

        // ---- stage P ----
        #pragma unroll
        for (int i = 0; i < 8; i++) {
            int r = ty * 4 + (i & 3) + (i >> 2) * 64;
            *(float4*)&sm[AT_PS + r * AT_PP + tx * 4] =
                make_float4(s[i][0], s[i][1], s[i][2], s[i][3]);
            *(float4*)&sm[AT_PS + r * AT_PP + tx * 4 + 64] =
                make_float4(s[i][4], s[i][5], s[i][6], s[i][7]);
        }
        __syncthreads();

        // ---- O += P @ V ----
        #pragma unroll 2
        for (int kv4 = 0; kv4 < 32; kv4++) {
            float pr[8][4];
            #pragma unroll
            for (int i = 0; i < 8; i++) {
                int r = ty * 4 + (i & 3) + (i >> 2) * 64;
                *(float4*)pr[i] = *(const float4*)&sm[AT_PS + r * AT_PP + kv4 * 4];
            }
            #pragma unroll
            for (int u = 0; u < 4; u++) {
                float4 v4 = *(const float4*)&sm[AT_VS + vb * AT_VSTG
                                                + (kv4 * 4 + u) * AT_VP + tx * 4];
                #pragma unroll
                for (int i = 0; i < 8; i++) {
                    float pu = pr[i][u];
                    o[i][0] += pu * v4.x; o[i][1] += pu * v4.y;
                    o[i][2] += pu * v4.z; o[i][3] += pu * v4.w;
                }
            }
        }
        // no trailing sync needed: next-iter hazards covered by wait+sync / mid-sync
    }

    // ---- epilogue ----
    #pragma unroll
    for (int i = 0; i < 8; i++) {
        int r = ty * 4 + (i & 3) + (i >> 2) * 64;
        float inv = 1.0f / lrow[i];
        float4 o4 = make_float4(o[i][0] * inv, o[i][1] * inv,
                                o[i][2] * inv, o[i][3] * inv);
        size_t off = ((size_t)b * S_ + q0 + r) * (H_ * A_) + h * A_ + tx * 4;
        *(float4*)(out + off) = o4;
    }
}

// ---------------------------------------------------------------------------
extern "C" void kernel_launch(void* const* d_in, const int* in_sizes, int n_in,
                              void* d_out, int out_size)
{
    const float* q  = (const float*)d_in[0];
    const float* k  = (const float*)d_in[1];
    const float* v  = (const float*)d_in[2];
    const float* Wq = (const float*)d_in[3];
    const float* bq = (const float*)d_in[4];
    const float* Wk = (const float*)d_in[5];
    const float* bk = (const float*)d_in[6];
    const float* Wv = (const float*)d_in[7];
    const float* bv = (const float*)d_in[8];
    float* out = (float*)d_out;

    static bool attr_set = false;  // idempotent attribute set
    if (!attr_set) {
        cudaFuncSetAttribute(proj_kernel,
                             cudaFuncAttributeMaxDynamicSharedMemorySize,
                             PK_SMEM_BYTES);
        cudaFuncSetAttribute(attn_kernel,
                             cudaFuncAttributeMaxDynamicSharedMemorySize,
                             AT_SMEM_BYTES);
        attr_set = true;
    }

    dim3 pgrid(S_ / 128, H_ / 2, 3 * B_);
    proj_kernel<<<pgrid, 256, PK_SMEM_BYTES>>>(q, k, v, Wq, bq, Wk, bk, Wv, bv);

    dim3 agrid(S_ / 128, H_, B_);
    attn_kernel<<<agrid, 256, AT_SMEM_BYTES>>>(out);
}